// round 15
// baseline (speedup 1.0000x reference)
#include <cuda_runtime.h>
#include <cuda_bf16.h>
#include <math.h>

#define PMAX 512
#define IMG_H 256
#define IMG_W 256
#define TILE_W 32
#define TILE_H 16
#define NTHREADS 512
#define TANFOV 0.5f
#define FXC (IMG_W / (2.0f * TANFOV))
#define FYC (IMG_H / (2.0f * TANFOV))
#define SH_C0 0.28209479177387814f

// Single fused kernel, one wave: 128 blocks (32x16-pixel tiles) x 512 threads.
// Each block redundantly computes per-Gaussian projection (1/thread), culls
// against its tile bbox (order-preserving ballot compaction), rank-sorts the
// survivors by depth, composites. Block (0,0) writes the radii/viewspace tail.
__global__ void __launch_bounds__(NTHREADS) fused_kernel(
    const float* __restrict__ points,
    const float* __restrict__ scales,
    const float* __restrict__ rots,
    const float* __restrict__ opacities,
    const float* __restrict__ shs,
    const float* __restrict__ vm,
    float* __restrict__ out, int out_size, int P)
{
    __shared__ float4 u0[PMAX];   // mx, my, -0.5A, -B
    __shared__ float4 u1[PMAX];   // -0.5C, op_eff, tpow, ex
    __shared__ float4 u2[PMAX];   // cr, cg, cb, ey
    __shared__ float  ukey[PMAX]; // depth key
    __shared__ short  sidx[PMAX]; // depth-sorted permutation of [0, n)
    __shared__ int    warp_cnt[16];
    __shared__ int    s_n;

    const float INF = __int_as_float(0x7f800000);
    int t = threadIdx.x;
    int lane = t & 31;
    int wid  = t >> 5;

    int tile_x0 = blockIdx.x * TILE_W;
    int tile_y0 = blockIdx.y * TILE_H;
    float bx0 = (float)tile_x0;
    float bx1 = (float)(tile_x0 + TILE_W - 1);
    float by0 = (float)tile_y0;
    float by1 = (float)(tile_y0 + TILE_H - 1);
    const int rgb_n = 3 * IMG_H * IMG_W;
    bool write_tail = ((blockIdx.x | blockIdx.y) == 0) && (out_size >= rgb_n + 4 * PMAX);

    // view matrix (broadcast loads)
    float W00 = vm[0], W01 = vm[1], W02 = vm[2],  T0 = vm[3];
    float W10 = vm[4], W11 = vm[5], W12 = vm[6],  T1 = vm[7];
    float W20 = vm[8], W21 = vm[9], W22 = vm[10], T2 = vm[11];

    // ---- per-Gaussian prep (1 Gaussian per thread) ----
    int i = t;

    float mx = 0.f, my = 0.f, Ah = 0.f, Bh = 0.f, Ch = 0.f;
    float op_eff = 0.f, tpow = INF, ex = 0.f, ey = 0.f;
    float cr = 0.f, cg = 0.f, cb = 0.f;
    float key = INF;
    int   radii = 0;

    if (i < P) {
        float s0 = __expf(scales[3*i+0]);
        float s1 = __expf(scales[3*i+1]);
        float s2 = __expf(scales[3*i+2]);

        float qr = rots[4*i+0], qx = rots[4*i+1], qy = rots[4*i+2], qz = rots[4*i+3];
        float qn = rsqrtf(qr*qr + qx*qx + qy*qy + qz*qz);
        qr *= qn; qx *= qn; qy *= qn; qz *= qn;
        float R00 = 1.f - 2.f*(qy*qy + qz*qz), R01 = 2.f*(qx*qy - qr*qz), R02 = 2.f*(qx*qz + qr*qy);
        float R10 = 2.f*(qx*qy + qr*qz), R11 = 1.f - 2.f*(qx*qx + qz*qz), R12 = 2.f*(qy*qz - qr*qx);
        float R20 = 2.f*(qx*qz - qr*qy), R21 = 2.f*(qy*qz + qr*qx), R22 = 1.f - 2.f*(qx*qx + qy*qy);

        float M00 = R00*s0, M01 = R01*s1, M02 = R02*s2;
        float M10 = R10*s0, M11 = R11*s1, M12 = R12*s2;
        float M20 = R20*s0, M21 = R21*s1, M22 = R22*s2;

        float S00 = M00*M00 + M01*M01 + M02*M02;
        float S01 = M00*M10 + M01*M11 + M02*M12;
        float S02 = M00*M20 + M01*M21 + M02*M22;
        float S11 = M10*M10 + M11*M11 + M12*M12;
        float S12 = M10*M20 + M11*M21 + M12*M22;
        float S22 = M20*M20 + M21*M21 + M22*M22;

        float px = points[3*i+0], py = points[3*i+1], pz = points[3*i+2];
        float tx = W00*px + W01*py + W02*pz + T0;
        float ty = W10*px + W11*py + W12*pz + T1;
        float tz = W20*px + W21*py + W22*pz + T2;

        bool visible = tz > 0.2f;
        float tzs = visible ? tz : 1.0f;

        const float lim = 1.3f * TANFOV;
        float txtz = fminf(fmaxf(tx/tzs, -lim), lim) * tzs;
        float tytz = fminf(fmaxf(ty/tzs, -lim), lim) * tzs;

        float inv_z  = 1.0f / tzs;
        float inv_z2 = inv_z * inv_z;
        float J00 = FXC * inv_z, J02 = -FXC * txtz * inv_z2;
        float J11 = FYC * inv_z, J12 = -FYC * tytz * inv_z2;

        float Tm00 = J00*W00 + J02*W20;
        float Tm01 = J00*W01 + J02*W21;
        float Tm02 = J00*W02 + J02*W22;
        float Tm10 = J11*W10 + J12*W20;
        float Tm11 = J11*W11 + J12*W21;
        float Tm12 = J11*W12 + J12*W22;

        float v00 = S00*Tm00 + S01*Tm01 + S02*Tm02;
        float v01 = S01*Tm00 + S11*Tm01 + S12*Tm02;
        float v02 = S02*Tm00 + S12*Tm01 + S22*Tm02;
        float v10 = S00*Tm10 + S01*Tm11 + S02*Tm12;
        float v11 = S01*Tm10 + S11*Tm11 + S12*Tm12;
        float v12 = S02*Tm10 + S12*Tm11 + S22*Tm12;
        float cov00 = Tm00*v00 + Tm01*v01 + Tm02*v02;
        float cov01 = Tm10*v00 + Tm11*v01 + Tm12*v02;
        float cov11 = Tm10*v10 + Tm11*v11 + Tm12*v12;

        float det_orig = cov00*cov11 - cov01*cov01;
        float a = cov00 + 0.3f;
        float c = cov11 + 0.3f;
        float b = cov01;
        float det = a*c - b*b;
        visible = visible && (det > 0.0f);
        float dets = (det > 0.0f) ? det : 1.0f;
        float comp = sqrtf(fmaxf(det_orig / dets, 0.0f));

        float opac = 1.0f / (1.0f + __expf(-opacities[i]));
        op_eff = opac * comp * (visible ? 1.0f : 0.0f);

        float inv_det = 1.0f / dets;
        Ah = -0.5f * (c * inv_det);
        Bh = b * inv_det;          // -conB
        Ch = -0.5f * (a * inv_det);

        float mid = 0.5f * (a + c);
        float lam = mid + sqrtf(fmaxf(mid*mid - det, 0.1f));
        radii = visible ? (int)ceilf(3.0f * sqrtf(lam)) : 0;

        mx = FXC * tx / tzs + (IMG_W - 1) * 0.5f;
        my = FYC * ty / tzs + (IMG_H - 1) * 0.5f;

        cr = fmaxf(shs[3*i+0] * SH_C0 + 0.5f, 0.0f);
        cg = fmaxf(shs[3*i+1] * SH_C0 + 0.5f, 0.0f);
        cb = fmaxf(shs[3*i+2] * SH_C0 + 0.5f, 0.0f);

        // log-space alpha cutoff (0.01 margin covers __expf/__logf rounding;
        // the per-pixel tests remain exact/authoritative)
        if (op_eff > 0.0f) tpow = -__logf(255.0f * op_eff) - 0.01f;
        else               tpow = INF;

        // exact conic bbox half-extents of the {power >= tpow} region
        if (tpow < 0.0f) {
            ex = sqrtf(fmaxf(-2.0f * tpow * a, 0.0f)) + 1e-3f;
            ey = sqrtf(fmaxf(-2.0f * tpow * c, 0.0f)) + 1e-3f;
        }

        key = visible ? tz : INF;
    }

    if (write_tail) {
        out[rgb_n + 3*i + 0] = 0.0f;
        out[rgb_n + 3*i + 1] = 0.0f;
        out[rgb_n + 3*i + 2] = 0.0f;
        out[rgb_n + 3*PMAX + i] = (float)radii;
    }

    // ---- order-preserving tile compaction (single round, 16 warps) ----
    bool pred = (tpow < 0.0f)
             && (mx + ex >= bx0) && (mx - ex <= bx1)
             && (my + ey >= by0) && (my - ey <= by1);
    unsigned m = __ballot_sync(0xffffffffu, pred);
    if (lane == 0) warp_cnt[wid] = __popc(m);
    int wprefix = __popc(m & ((1u << lane) - 1u));
    __syncthreads();
    int woff = 0, tot = 0;
    #pragma unroll
    for (int w = 0; w < 16; w++) {
        int cnt = warp_cnt[w];
        woff += (w < wid) ? cnt : 0;
        tot  += cnt;
    }
    if (pred) {
        int pos = woff + wprefix;
        u0[pos] = make_float4(mx, my, Ah, Bh);
        u1[pos] = make_float4(Ch, op_eff, tpow, ex);
        u2[pos] = make_float4(cr, cg, cb, ey);
        ukey[pos] = key;
    }
    if (t == 0) s_n = tot;
    __syncthreads();
    int n = s_n;

    // ---- stable rank-sort of the survivors by depth ----
    // Compaction preserved original-index order, so tie-break by compacted
    // position reproduces jnp.argsort's stable semantics exactly.
    for (int e = t; e < n; e += NTHREADS) {
        float ke = ukey[e];
        int rank = 0;
        for (int j = 0; j < n; j++) {
            float kj = ukey[j];
            rank += (kj < ke) || (kj == ke && j < e);
        }
        sidx[rank] = (short)e;
    }
    __syncthreads();

    // ---- per-pixel compositing over the culled, depth-ordered list ----
    int px = tile_x0 + (t & (TILE_W - 1));
    int py = tile_y0 + (t >> 5);
    float fx = (float)px;
    float fy = (float)py;

    float T = 1.0f;
    float pr = 0.0f, pg = 0.0f, pb = 0.0f;

    for (int k = 0; k < n; k++) {
        int j = sidx[k];
        float4 a = u0[j];
        float4 b = u1[j];
        float dx = fx - a.x;
        float dy = fy - a.y;
        // power = A'*dx^2 + C'*dy^2 + B'*dx*dy   (A'=-0.5A, C'=-0.5C, B'=-B)
        float power = fmaf(a.z, dx * dx, fmaf(b.x, dy * dy, a.w * dx * dy));
        if (power > 0.0f || power < b.z) continue;   // b.z = tpow cutoff
        float alpha = fminf(0.99f, b.y * __expf(power));
        if (alpha < 0.003921569f) continue;          // 1/255
        float w = alpha * T;
        float4 c = u2[j];
        pr = fmaf(w, c.x, pr);
        pg = fmaf(w, c.y, pg);
        pb = fmaf(w, c.z, pb);
        T *= (1.0f - alpha);
        if (T < 1e-4f) break;                        // Texcl monotone nonincreasing
    }

    int idx = py * IMG_W + px;
    out[idx]                     = pr;
    out[IMG_H * IMG_W + idx]     = pg;
    out[2 * IMG_H * IMG_W + idx] = pb;
}

extern "C" void kernel_launch(void* const* d_in, const int* in_sizes, int n_in,
                              void* d_out, int out_size)
{
    const float* points    = (const float*)d_in[0];
    const float* scales    = (const float*)d_in[1];
    const float* rots      = (const float*)d_in[2];
    const float* opacities = (const float*)d_in[3];
    const float* shs       = (const float*)d_in[4];
    const float* viewmat   = (const float*)d_in[5];
    float* out = (float*)d_out;

    int P = in_sizes[0] / 3;
    if (P > PMAX) P = PMAX;

    fused_kernel<<<dim3(IMG_W / TILE_W, IMG_H / TILE_H), NTHREADS>>>(
        points, scales, rots, opacities, shs, viewmat, out, out_size, P);
}